// round 15
// baseline (speedup 1.0000x reference)
#include <cuda_runtime.h>
#include <cuda_bf16.h>
#include <mma.h>

using namespace nvcuda;

#define BATCH 4
#define CH    512
#define HH    256
#define WWD   256
#define NN    1024
#define KD    64
#define MQKV  640

// ---------------- device scratch ----------------
__device__ __nv_bfloat16 g_xf[BATCH * CH * NN];          // [b][c][n]
__device__ __nv_bfloat16 g_wcat[MQKV * CH];              // [m][c]
__device__ float         g_bcat[MQKV];
__device__ __nv_bfloat16 g_qkv[BATCH * MQKV * NN];       // [b][m][n]
__device__ __nv_bfloat16 g_energy[BATCH * NN * NN];      // [b][n][m]
__device__ __nv_bfloat16 g_attn[BATCH * NN * NN];        // [b][m][n]
__device__ float         g_osmall[2 * BATCH * CH * NN];  // 2 k-split parts

// ---------------- cp.async helpers ----------------
__device__ __forceinline__ void cp16(void* smem, const void* gmem) {
    unsigned s = (unsigned)__cvta_generic_to_shared(smem);
    asm volatile("cp.async.cg.shared.global [%0], [%1], 16;\n" :: "r"(s), "l"(gmem));
}
__device__ __forceinline__ void cp_commit() {
    asm volatile("cp.async.commit_group;\n" ::: "memory");
}
template <int N>
__device__ __forceinline__ void cp_wait() {
    asm volatile("cp.async.wait_group %0;\n" :: "n"(N) : "memory");
}

// ---------------- 1) avg-pool 8x8 -> bf16 ----------------
__global__ __launch_bounds__(256) void pool_kernel(const float* __restrict__ x) {
    unsigned idx = blockIdx.x * 256u + threadIdx.x;   // over BATCH*CH*32*32
    unsigned ww = idx & 31u;
    unsigned t  = idx >> 5;
    unsigned hh = t & 31u;
    t >>= 5;                                          // b*512 + c
    const float* p = x + (size_t)t * (HH * WWD) + (size_t)(hh * 8) * WWD + ww * 8;
    float s = 0.f;
#pragma unroll
    for (int r = 0; r < 8; ++r) {
        float4 a = __ldcs(reinterpret_cast<const float4*>(p + (size_t)r * WWD));
        float4 b = __ldcs(reinterpret_cast<const float4*>(p + (size_t)r * WWD + 4));
        s += (a.x + a.y) + (a.z + a.w) + (b.x + b.y) + (b.z + b.w);
    }
    g_xf[idx] = __float2bfloat16(s * (1.f / 64.f));
}

// ---------------- 2) prep ----------------
__global__ __launch_bounds__(256) void prep_w(const float* __restrict__ Wq,
                                              const float* __restrict__ Wk,
                                              const float* __restrict__ Wv,
                                              const float* __restrict__ bq,
                                              const float* __restrict__ bk,
                                              const float* __restrict__ bv) {
    unsigned i = blockIdx.x * 256u + threadIdx.x;
    if (i < MQKV * CH) {
        unsigned m = i >> 9, c = i & 511u;
        float v;
        if (m < 64)       v = Wq[m * 512 + c];
        else if (m < 128) v = Wk[(m - 64) * 512 + c];
        else              v = Wv[(m - 128) * 512 + c];
        g_wcat[i] = __float2bfloat16(v);
    }
    if (i < MQKV) {
        float b;
        if (i < 64)       b = bq[i];
        else if (i < 128) b = bk[i - 64];
        else              b = bv[i - 128];
        g_bcat[i] = b;
    }
}

// ---------------- bf16 GEMM: 128x128 tile, BK=64, STAGES-deep pipeline ------
// blockIdx.z encodes (part, batch): b = z & 3, p = z >> 2 (k-split part).
// C (MxN row-major) = A(MxK) * B(KxN)
// ACOL: A(m,k) at A[k*lda+m]; BCOL: B(k,n) at B[n*ldb+k]
// BF16OUT: stage through smem, add bias[m] (nullable), store bf16.
//          else: store fp32 direct (with k-split part offset sCpart).
// PDLSYNC: prefetch A chunk0 (finalized before PDL predecessor), gridsync,
//          then all B loads.
template <int STAGES, bool ACOL, bool BCOL, bool BF16OUT, bool PDLSYNC>
__global__ __launch_bounds__(256) void gemm_bf16(
    const __nv_bfloat16* __restrict__ A, int lda, size_t sA,
    const __nv_bfloat16* __restrict__ B, int ldb, size_t sB,
    void* __restrict__ C, int ldc, size_t sC, size_t sCpart,
    const float* __restrict__ bias, int Kdim) {

    cudaTriggerProgrammaticLaunchCompletion();   // allow PDL successor

    constexpr int AR = ACOL ? 64 : 128;
    constexpr int AC = ACOL ? 136 : 72;
    constexpr int BR = BCOL ? 128 : 64;
    constexpr int BC = BCOL ? 72 : 136;
    extern __shared__ __align__(16) __nv_bfloat16 smem[];
    __nv_bfloat16* As = smem;                         // [STAGES][AR][AC]
    __nv_bfloat16* Bs = smem + STAGES * AR * AC;      // [STAGES][BR][BC]

    const unsigned z = blockIdx.z;
    const unsigned bb = z & 3u;
    const unsigned pp = z >> 2;

    const __nv_bfloat16* Ab = A + sA * bb + (ACOL ? (size_t)pp * Kdim * lda : (size_t)pp * Kdim);
    const __nv_bfloat16* Bb = B + sB * bb + (BCOL ? (size_t)pp * Kdim : (size_t)pp * Kdim * ldb);

    const int row0 = blockIdx.y * 128;
    const int col0 = blockIdx.x * 128;
    const unsigned tid  = threadIdx.x;
    const unsigned warp = tid >> 5;
    const unsigned lane = tid & 31u;
    const int wm = warp & 3;
    const int wn = warp >> 2;

    wmma::fragment<wmma::accumulator, 16, 16, 16, float> acc[2][4];
#pragma unroll
    for (int sm = 0; sm < 2; ++sm)
#pragma unroll
        for (int sn = 0; sn < 4; ++sn)
            wmma::fill_fragment(acc[sm][sn], 0.f);

    const int nChunks = Kdim >> 6;

    auto loadA = [&](int c, int buf) {
        int k0 = c << 6;
        __nv_bfloat16* Ad = As + buf * (AR * AC);
#pragma unroll
        for (int i = 0; i < 4; ++i) {
            unsigned f = tid + i * 256u;
            if (ACOL) {
                unsigned kk = f >> 4, mq = f & 15u;
                cp16(Ad + kk * AC + mq * 8, Ab + (size_t)(k0 + kk) * lda + row0 + mq * 8);
            } else {
                unsigned r = f >> 3, kq = f & 7u;
                cp16(Ad + r * AC + kq * 8, Ab + (size_t)(row0 + r) * lda + k0 + kq * 8);
            }
        }
    };
    auto loadB = [&](int c, int buf) {
        int k0 = c << 6;
        __nv_bfloat16* Bd = Bs + buf * (BR * BC);
#pragma unroll
        for (int i = 0; i < 4; ++i) {
            unsigned f = tid + i * 256u;
            if (BCOL) {
                unsigned nn2 = f >> 3, kq = f & 7u;
                cp16(Bd + nn2 * BC + kq * 8, Bb + (size_t)(col0 + nn2) * ldb + k0 + kq * 8);
            } else {
                unsigned kk = f >> 4, nq = f & 15u;
                cp16(Bd + kk * BC + nq * 8, Bb + (size_t)(k0 + kk) * ldb + col0 + nq * 8);
            }
        }
    };

    // prologue: chunk 0 (A independent of PDL predecessor; B is not),
    // then chunk 1 when 3-stage.
    loadA(0, 0);
    if (PDLSYNC) cudaGridDependencySynchronize();
    loadB(0, 0);
    cp_commit();
    if (STAGES == 3 && nChunks > 1) {
        loadA(1, 1);
        loadB(1, 1);
        cp_commit();
    }

    for (int c = 0; c < nChunks; ++c) {
        int buf = c % STAGES;
        if (STAGES == 3) {
            if (c + 2 < nChunks) {
                loadA(c + 2, (c + 2) % 3);
                loadB(c + 2, (c + 2) % 3);
                cp_commit();
                cp_wait<2>();
            } else if (c + 1 < nChunks) {
                cp_wait<1>();
            } else {
                cp_wait<0>();
            }
        } else {
            if (c + 1 < nChunks) {
                loadA(c + 1, (c + 1) & 1);
                loadB(c + 1, (c + 1) & 1);
                cp_commit();
                cp_wait<1>();
            } else {
                cp_wait<0>();
            }
        }
        __syncthreads();

        const __nv_bfloat16* Ad = As + buf * (AR * AC);
        const __nv_bfloat16* Bd = Bs + buf * (BR * BC);
#pragma unroll
        for (int ks = 0; ks < 64; ks += 16) {
            using ARow = wmma::fragment<wmma::matrix_a, 16, 16, 16, __nv_bfloat16, wmma::row_major>;
            using ACol = wmma::fragment<wmma::matrix_a, 16, 16, 16, __nv_bfloat16, wmma::col_major>;
            using BRow = wmma::fragment<wmma::matrix_b, 16, 16, 16, __nv_bfloat16, wmma::row_major>;
            using BCol = wmma::fragment<wmma::matrix_b, 16, 16, 16, __nv_bfloat16, wmma::col_major>;
            typename std::conditional<ACOL, ACol, ARow>::type af[2];
            typename std::conditional<BCOL, BCol, BRow>::type bf[4];
#pragma unroll
            for (int sm = 0; sm < 2; ++sm) {
                const __nv_bfloat16* ap = ACOL ? Ad + ks * AC + wm * 32 + sm * 16
                                               : Ad + (wm * 32 + sm * 16) * AC + ks;
                wmma::load_matrix_sync(af[sm], ap, AC);
            }
#pragma unroll
            for (int sn = 0; sn < 4; ++sn) {
                const __nv_bfloat16* bp = BCOL ? Bd + (wn * 64 + sn * 16) * BC + ks
                                               : Bd + ks * BC + wn * 64 + sn * 16;
                wmma::load_matrix_sync(bf[sn], bp, BC);
            }
#pragma unroll
            for (int sm = 0; sm < 2; ++sm)
#pragma unroll
                for (int sn = 0; sn < 4; ++sn)
                    wmma::mma_sync(acc[sm][sn], af[sm], bf[sn], acc[sm][sn]);
        }
        __syncthreads();
    }

    if (BF16OUT) {
        __syncthreads();
        __nv_bfloat16* Cb = (__nv_bfloat16*)C + sC * bb;
        float* stage = reinterpret_cast<float*>(As) + warp * 320;  // 16x20 per warp
        const int r  = lane >> 1;
        const int c8 = (lane & 1) * 8;
#pragma unroll
        for (int sm = 0; sm < 2; ++sm) {
            const int gr = row0 + wm * 32 + sm * 16 + r;
            const float bv = bias ? bias[gr] : 0.f;
#pragma unroll
            for (int sn = 0; sn < 4; ++sn) {
                wmma::store_matrix_sync(stage, acc[sm][sn], 20, wmma::mem_row_major);
                __syncwarp();
                __nv_bfloat16 tmp[8];
#pragma unroll
                for (int j = 0; j < 8; ++j)
                    tmp[j] = __float2bfloat16(stage[r * 20 + c8 + j] + bv);
                *reinterpret_cast<uint4*>(Cb + (size_t)gr * ldc + col0 + wn * 64 + sn * 16 + c8) =
                    *reinterpret_cast<uint4*>(tmp);
                __syncwarp();
            }
        }
    } else {
        float* Cb = (float*)C + sC * bb + sCpart * pp;
#pragma unroll
        for (int sm = 0; sm < 2; ++sm)
#pragma unroll
            for (int sn = 0; sn < 4; ++sn) {
                float* cp = Cb + (size_t)(row0 + wm * 32 + sm * 16) * ldc + col0 + wn * 64 + sn * 16;
                wmma::store_matrix_sync(cp, acc[sm][sn], ldc, wmma::mem_row_major);
            }
    }
}

// ---------------- softmax (scale 0.125 fused), bf16 in -> bf16 out ---------
__global__ __launch_bounds__(256) void softmax_kernel() {
    cudaTriggerProgrammaticLaunchCompletion();   // let out-GEMM (PDL) come up
    unsigned row = blockIdx.x;                        // b*1024 + n
    const __nv_bfloat162* er =
        reinterpret_cast<const __nv_bfloat162*>(g_energy + (size_t)row * NN);
    __nv_bfloat16* ar = g_attn + (size_t)row * NN;
    unsigned tid = threadIdx.x;

    __nv_bfloat162 ea = er[tid * 2];
    __nv_bfloat162 eb = er[tid * 2 + 1];
    const float s = 0.125f;
    float v0 = __bfloat162float(ea.x) * s, v1 = __bfloat162float(ea.y) * s;
    float v2 = __bfloat162float(eb.x) * s, v3 = __bfloat162float(eb.y) * s;

    __shared__ float red[8];
    float mx = fmaxf(fmaxf(v0, v1), fmaxf(v2, v3));
#pragma unroll
    for (int o = 16; o > 0; o >>= 1) mx = fmaxf(mx, __shfl_xor_sync(0xffffffffu, mx, o));
    if ((tid & 31u) == 0) red[tid >> 5] = mx;
    __syncthreads();
    float m = red[0];
#pragma unroll
    for (int i = 1; i < 8; ++i) m = fmaxf(m, red[i]);

    float e0 = __expf(v0 - m), e1 = __expf(v1 - m), e2 = __expf(v2 - m), e3 = __expf(v3 - m);
    float sum = (e0 + e1) + (e2 + e3);
#pragma unroll
    for (int o = 16; o > 0; o >>= 1) sum += __shfl_xor_sync(0xffffffffu, sum, o);
    __syncthreads();
    if ((tid & 31u) == 0) red[tid >> 5] = sum;
    __syncthreads();
    float tot = 0.f;
#pragma unroll
    for (int i = 0; i < 8; ++i) tot += red[i];

    float inv = 1.f / tot;
    __nv_bfloat162 p0, p1;
    p0.x = __float2bfloat16(e0 * inv);
    p0.y = __float2bfloat16(e1 * inv);
    p1.x = __float2bfloat16(e2 * inv);
    p1.y = __float2bfloat16(e3 * inv);
    reinterpret_cast<__nv_bfloat162*>(ar)[tid * 2]     = p0;
    reinterpret_cast<__nv_bfloat162*>(ar)[tid * 2 + 1] = p1;
}

// ---------------- upsample x8 + residual (sums 2 k-split parts) -------------
// PDL secondary with deep prefetch: 8 slab-strided x float4s loaded BEFORE
// the grid-dependency sync; osmall read + out store after the sync.
#define UPS_STRIDE ((size_t)(BATCH * CH * HH * WWD / 4) / 8)   // float4 per slab
__global__ __launch_bounds__(256) void upsample_add(const float* __restrict__ x,
                                                    float* __restrict__ out) {
    size_t g = (size_t)blockIdx.x * 256u + threadIdx.x;
    float4 xv[8];
#pragma unroll
    for (int j = 0; j < 8; ++j)
        xv[j] = __ldcs(reinterpret_cast<const float4*>(x) + g + (size_t)j * UPS_STRIDE);

    cudaGridDependencySynchronize();   // wait for out-GEMM grid completion

#pragma unroll
    for (int j = 0; j < 8; ++j) {
        size_t i = g + (size_t)j * UPS_STRIDE;
        unsigned w4 = (unsigned)(i & 63);
        size_t t = i >> 6;
        unsigned y = (unsigned)(t & 255);
        size_t bc = t >> 8;                                   // b*512 + c
        size_t oi = (bc << 10) + ((size_t)(y >> 3) << 5) + (w4 >> 1);
        float add = g_osmall[oi] + g_osmall[oi + (size_t)BATCH * CH * NN];
        __stcs(reinterpret_cast<float4*>(out) + i,
               make_float4(xv[j].x + add, xv[j].y + add, xv[j].z + add, xv[j].w + add));
    }
}

// ---------------- launch ----------------------------------------------------
extern "C" void kernel_launch(void* const* d_in, const int* in_sizes, int n_in,
                              void* d_out, int out_size) {
    const float* x  = (const float*)d_in[0];
    const float* Wq = (const float*)d_in[1];
    const float* bq = (const float*)d_in[2];
    const float* Wk = (const float*)d_in[3];
    const float* bk = (const float*)d_in[4];
    const float* Wv = (const float*)d_in[5];
    const float* bv = (const float*)d_in[6];
    float* out = (float*)d_out;

    __nv_bfloat16 *xf, *wcat, *qkv, *attn, *energy;
    float *osmall, *bcat;
    cudaGetSymbolAddress((void**)&xf,     g_xf);
    cudaGetSymbolAddress((void**)&wcat,   g_wcat);
    cudaGetSymbolAddress((void**)&bcat,   g_bcat);
    cudaGetSymbolAddress((void**)&qkv,    g_qkv);
    cudaGetSymbolAddress((void**)&energy, g_energy);
    cudaGetSymbolAddress((void**)&attn,   g_attn);
    cudaGetSymbolAddress((void**)&osmall, g_osmall);

    auto QKV = gemm_bf16<3, false, false, true,  false>;   // 3-stage pipeline
    auto ENE = gemm_bf16<2, true,  false, true,  false>;   // K=64: 1 chunk
    auto OUT = gemm_bf16<3, false, true,  false, true>;    // 3-stage + PDL

    constexpr int SM_QKV = 3 * (128 * 72 + 64 * 136) * 2;   // 107520
    constexpr int SM_ENE = 2 * (64 * 136 + 64 * 136) * 2;   // 69632
    constexpr int SM_OUT = 3 * (128 * 72 + 128 * 72) * 2;   // 110592
    cudaFuncSetAttribute(QKV, cudaFuncAttributeMaxDynamicSharedMemorySize, SM_QKV);
    cudaFuncSetAttribute(ENE, cudaFuncAttributeMaxDynamicSharedMemorySize, SM_ENE);
    cudaFuncSetAttribute(OUT, cudaFuncAttributeMaxDynamicSharedMemorySize, SM_OUT);

    cudaLaunchAttribute pdl[1];
    pdl[0].id = cudaLaunchAttributeProgrammaticStreamSerialization;
    pdl[0].val.programmaticStreamSerializationAllowed = 1;

    pool_kernel<<<(BATCH * CH * NN) / 256, 256>>>(x);
    prep_w<<<(MQKV * CH + 255) / 256, 256>>>(Wq, Wk, Wv, bq, bk, bv);

    // QKV: qkv[b][m][n] = bias[m] + sum_c wcat[m][c] * xf[b][c][n]  (bf16 out)
    {
        dim3 g(NN / 128, MQKV / 128, BATCH);
        QKV<<<g, 256, SM_QKV>>>(
            wcat, 512, 0,
            xf,   NN,  (size_t)CH * NN,
            qkv,  NN,  (size_t)MQKV * NN, 0,
            bcat, CH);
    }
    // energy[b][n][m] = sum_k q[b][k][n] * kmat[b][k][m]   (bf16 out, K=64)
    {
        dim3 g(NN / 128, NN / 128, BATCH);
        ENE<<<g, 256, SM_ENE>>>(
            qkv,           NN, (size_t)MQKV * NN,
            qkv + 64 * NN, NN, (size_t)MQKV * NN,
            energy,        NN, (size_t)NN * NN, 0,
            nullptr, KD);
    }
    softmax_kernel<<<BATCH * NN, 256>>>();
    // out-GEMM (PDL after softmax): prefetch V chunk0 (finalized by QKV,
    // before softmax started), gridsync, then attn. k-split x2, fp32 out.
    {
        cudaLaunchConfig_t cfg = {};
        cfg.gridDim = dim3(NN / 128, CH / 128, BATCH * 2);
        cfg.blockDim = dim3(256, 1, 1);
        cfg.dynamicSmemBytes = SM_OUT;
        cfg.stream = 0;
        cfg.attrs = pdl; cfg.numAttrs = 1;
        cudaLaunchKernelEx(&cfg, OUT,
            (const __nv_bfloat16*)(qkv + 128 * NN), NN, (size_t)MQKV * NN,
            (const __nv_bfloat16*)attn,             NN, (size_t)NN * NN,
            (void*)osmall, NN, (size_t)CH * NN, (size_t)BATCH * CH * NN,
            (const float*)nullptr, NN / 2);
    }
    // upsample (PDL after out-GEMM): deep 8-slab x prefetch, gridsync, store.
    {
        cudaLaunchConfig_t cfg = {};
        cfg.gridDim  = dim3((unsigned)(UPS_STRIDE / 256), 1, 1);
        cfg.blockDim = dim3(256, 1, 1);
        cfg.dynamicSmemBytes = 0;
        cfg.stream = 0;
        cfg.attrs = pdl; cfg.numAttrs = 1;
        cudaLaunchKernelEx(&cfg, upsample_add, x, out);
    }
}

// round 16
// speedup vs baseline: 1.1017x; 1.1017x over previous
#include <cuda_runtime.h>
#include <cuda_bf16.h>
#include <mma.h>

using namespace nvcuda;

#define BATCH 4
#define CH    512
#define HH    256
#define WWD   256
#define NN    1024
#define KD    64
#define MQKV  640

// ---------------- device scratch ----------------
__device__ __nv_bfloat16 g_xf[BATCH * CH * NN];          // [b][c][n]
__device__ __nv_bfloat16 g_wcat[MQKV * CH];              // [m][c]
__device__ float         g_bcat[MQKV];
__device__ __nv_bfloat16 g_qkv[BATCH * MQKV * NN];       // [b][m][n]
__device__ __nv_bfloat16 g_attn[BATCH * NN * NN];        // unnormalized exp(e/8)
__device__ float         g_ssum[BATCH * NN];             // softmax row sums
__device__ float         g_osmall[2 * BATCH * CH * NN];  // 2 k-split parts

// ---------------- cp.async helpers ----------------
__device__ __forceinline__ void cp16(void* smem, const void* gmem) {
    unsigned s = (unsigned)__cvta_generic_to_shared(smem);
    asm volatile("cp.async.cg.shared.global [%0], [%1], 16;\n" :: "r"(s), "l"(gmem));
}
__device__ __forceinline__ void cp_commit() {
    asm volatile("cp.async.commit_group;\n" ::: "memory");
}
template <int N>
__device__ __forceinline__ void cp_wait() {
    asm volatile("cp.async.wait_group %0;\n" :: "n"(N) : "memory");
}

// ---------------- 1) avg-pool 8x8 -> bf16 ----------------
__global__ __launch_bounds__(256) void pool_kernel(const float* __restrict__ x) {
    unsigned idx = blockIdx.x * 256u + threadIdx.x;   // over BATCH*CH*32*32
    unsigned ww = idx & 31u;
    unsigned t  = idx >> 5;
    unsigned hh = t & 31u;
    t >>= 5;                                          // b*512 + c
    const float* p = x + (size_t)t * (HH * WWD) + (size_t)(hh * 8) * WWD + ww * 8;
    float s = 0.f;
#pragma unroll
    for (int r = 0; r < 8; ++r) {
        float4 a = __ldcs(reinterpret_cast<const float4*>(p + (size_t)r * WWD));
        float4 b = __ldcs(reinterpret_cast<const float4*>(p + (size_t)r * WWD + 4));
        s += (a.x + a.y) + (a.z + a.w) + (b.x + b.y) + (b.z + b.w);
    }
    g_xf[idx] = __float2bfloat16(s * (1.f / 64.f));
}

// ---------------- 2) prep (also zeroes softmax row sums) ----------------
__global__ __launch_bounds__(256) void prep_w(const float* __restrict__ Wq,
                                              const float* __restrict__ Wk,
                                              const float* __restrict__ Wv,
                                              const float* __restrict__ bq,
                                              const float* __restrict__ bk,
                                              const float* __restrict__ bv) {
    unsigned i = blockIdx.x * 256u + threadIdx.x;
    if (i < MQKV * CH) {
        unsigned m = i >> 9, c = i & 511u;
        float v;
        if (m < 64)       v = Wq[m * 512 + c];
        else if (m < 128) v = Wk[(m - 64) * 512 + c];
        else              v = Wv[(m - 128) * 512 + c];
        g_wcat[i] = __float2bfloat16(v);
    }
    if (i < MQKV) {
        float b;
        if (i < 64)       b = bq[i];
        else if (i < 128) b = bk[i - 64];
        else              b = bv[i - 128];
        g_bcat[i] = b;
    }
    if (i < BATCH * NN) g_ssum[i] = 0.f;
}

// ---------------- bf16 GEMM: 128x128 tile, BK=64, dyn smem double buffer ----
// blockIdx.z encodes (part, batch): b = z & 3, p = z >> 2 (k-split part).
// C (MxN row-major) = A(MxK) * B(KxN)
// ACOL: A(m,k) at A[k*lda+m]; BCOL: B(k,n) at B[n*ldb+k]
// OUTMODE: 0 = bf16 + bias[m]; 1 = bf16 exp(0.125*acc) + row-sum atomics into
//          g_ssum[bb*NN + row]; 2 = fp32 direct (k-split offset sCpart).
// PDLSYNC: prefetch A chunk0 (finalized before PDL predecessor), gridsync, B.
template <bool ACOL, bool BCOL, int OUTMODE, bool PDLSYNC>
__global__ __launch_bounds__(256) void gemm_bf16(
    const __nv_bfloat16* __restrict__ A, int lda, size_t sA,
    const __nv_bfloat16* __restrict__ B, int ldb, size_t sB,
    void* __restrict__ C, int ldc, size_t sC, size_t sCpart,
    const float* __restrict__ bias, int Kdim) {

    cudaTriggerProgrammaticLaunchCompletion();   // allow PDL successor

    constexpr int AR = ACOL ? 64 : 128;
    constexpr int AC = ACOL ? 136 : 72;
    constexpr int BR = BCOL ? 128 : 64;
    constexpr int BC = BCOL ? 72 : 136;
    extern __shared__ __align__(16) __nv_bfloat16 smem[];
    __nv_bfloat16* As = smem;                    // [2][AR][AC]
    __nv_bfloat16* Bs = smem + 2 * AR * AC;      // [2][BR][BC]

    const unsigned z = blockIdx.z;
    const unsigned bb = z & 3u;
    const unsigned pp = z >> 2;

    const __nv_bfloat16* Ab = A + sA * bb + (ACOL ? (size_t)pp * Kdim * lda : (size_t)pp * Kdim);
    const __nv_bfloat16* Bb = B + sB * bb + (BCOL ? (size_t)pp * Kdim : (size_t)pp * Kdim * ldb);

    const int row0 = blockIdx.y * 128;
    const int col0 = blockIdx.x * 128;
    const unsigned tid  = threadIdx.x;
    const unsigned warp = tid >> 5;
    const unsigned lane = tid & 31u;
    const int wm = warp & 3;
    const int wn = warp >> 2;

    wmma::fragment<wmma::accumulator, 16, 16, 16, float> acc[2][4];
#pragma unroll
    for (int sm = 0; sm < 2; ++sm)
#pragma unroll
        for (int sn = 0; sn < 4; ++sn)
            wmma::fill_fragment(acc[sm][sn], 0.f);

    const int nChunks = Kdim >> 6;

    auto loadA = [&](int c, int buf) {
        int k0 = c << 6;
        __nv_bfloat16* Ad = As + buf * (AR * AC);
#pragma unroll
        for (int i = 0; i < 4; ++i) {
            unsigned f = tid + i * 256u;
            if (ACOL) {
                unsigned kk = f >> 4, mq = f & 15u;
                cp16(Ad + kk * AC + mq * 8, Ab + (size_t)(k0 + kk) * lda + row0 + mq * 8);
            } else {
                unsigned r = f >> 3, kq = f & 7u;
                cp16(Ad + r * AC + kq * 8, Ab + (size_t)(row0 + r) * lda + k0 + kq * 8);
            }
        }
    };
    auto loadB = [&](int c, int buf) {
        int k0 = c << 6;
        __nv_bfloat16* Bd = Bs + buf * (BR * BC);
#pragma unroll
        for (int i = 0; i < 4; ++i) {
            unsigned f = tid + i * 256u;
            if (BCOL) {
                unsigned nn2 = f >> 3, kq = f & 7u;
                cp16(Bd + nn2 * BC + kq * 8, Bb + (size_t)(col0 + nn2) * ldb + k0 + kq * 8);
            } else {
                unsigned kk = f >> 4, nq = f & 15u;
                cp16(Bd + kk * BC + nq * 8, Bb + (size_t)(k0 + kk) * ldb + col0 + nq * 8);
            }
        }
    };

    // chunk 0: A finalized before the PDL predecessor started; B is not.
    loadA(0, 0);
    if (PDLSYNC) cudaGridDependencySynchronize();
    loadB(0, 0);
    cp_commit();

    for (int c = 0; c < nChunks; ++c) {
        int buf = c & 1;
        if (c + 1 < nChunks) {
            loadA(c + 1, (c + 1) & 1);
            loadB(c + 1, (c + 1) & 1);
            cp_commit();
            cp_wait<1>();
        } else {
            cp_wait<0>();
        }
        __syncthreads();

        const __nv_bfloat16* Ad = As + buf * (AR * AC);
        const __nv_bfloat16* Bd = Bs + buf * (BR * BC);
#pragma unroll
        for (int ks = 0; ks < 64; ks += 16) {
            using ARow = wmma::fragment<wmma::matrix_a, 16, 16, 16, __nv_bfloat16, wmma::row_major>;
            using ACol = wmma::fragment<wmma::matrix_a, 16, 16, 16, __nv_bfloat16, wmma::col_major>;
            using BRow = wmma::fragment<wmma::matrix_b, 16, 16, 16, __nv_bfloat16, wmma::row_major>;
            using BCol = wmma::fragment<wmma::matrix_b, 16, 16, 16, __nv_bfloat16, wmma::col_major>;
            typename std::conditional<ACOL, ACol, ARow>::type af[2];
            typename std::conditional<BCOL, BCol, BRow>::type bf[4];
#pragma unroll
            for (int sm = 0; sm < 2; ++sm) {
                const __nv_bfloat16* ap = ACOL ? Ad + ks * AC + wm * 32 + sm * 16
                                               : Ad + (wm * 32 + sm * 16) * AC + ks;
                wmma::load_matrix_sync(af[sm], ap, AC);
            }
#pragma unroll
            for (int sn = 0; sn < 4; ++sn) {
                const __nv_bfloat16* bp = BCOL ? Bd + (wn * 64 + sn * 16) * BC + ks
                                               : Bd + ks * BC + wn * 64 + sn * 16;
                wmma::load_matrix_sync(bf[sn], bp, BC);
            }
#pragma unroll
            for (int sm = 0; sm < 2; ++sm)
#pragma unroll
                for (int sn = 0; sn < 4; ++sn)
                    wmma::mma_sync(acc[sm][sn], af[sm], bf[sn], acc[sm][sn]);
        }
        __syncthreads();
    }

    if (OUTMODE == 0 || OUTMODE == 1) {
        __syncthreads();
        __nv_bfloat16* Cb = (__nv_bfloat16*)C + sC * bb;
        float* stage = reinterpret_cast<float*>(As) + warp * 320;  // 16x20 per warp
        const int r  = lane >> 1;
        const int c8 = (lane & 1) * 8;
#pragma unroll
        for (int sm = 0; sm < 2; ++sm) {
            const int gr = row0 + wm * 32 + sm * 16 + r;
            const float bv = (OUTMODE == 0 && bias) ? bias[gr] : 0.f;
            float rsum = 0.f;
#pragma unroll
            for (int sn = 0; sn < 4; ++sn) {
                wmma::store_matrix_sync(stage, acc[sm][sn], 20, wmma::mem_row_major);
                __syncwarp();
                __nv_bfloat16 tmp[8];
#pragma unroll
                for (int j = 0; j < 8; ++j) {
                    float v = stage[r * 20 + c8 + j];
                    if (OUTMODE == 1) {
                        float p = __expf(v * 0.125f);
                        rsum += p;
                        tmp[j] = __float2bfloat16(p);
                    } else {
                        tmp[j] = __float2bfloat16(v + bv);
                    }
                }
                *reinterpret_cast<uint4*>(Cb + (size_t)gr * ldc + col0 + wn * 64 + sn * 16 + c8) =
                    *reinterpret_cast<uint4*>(tmp);
                __syncwarp();
            }
            if (OUTMODE == 1)
                atomicAdd(&g_ssum[bb * NN + gr], rsum);
        }
    } else {
        float* Cb = (float*)C + sC * bb + sCpart * pp;
#pragma unroll
        for (int sm = 0; sm < 2; ++sm)
#pragma unroll
            for (int sn = 0; sn < 4; ++sn) {
                float* cp = Cb + (size_t)(row0 + wm * 32 + sm * 16) * ldc + col0 + wn * 64 + sn * 16;
                wmma::store_matrix_sync(cp, acc[sm][sn], ldc, wmma::mem_row_major);
            }
    }
}

// ---------------- upsample x8 + residual (k-split sum + softmax norm) -------
// PDL secondary with deep prefetch: 8 slab-strided x float4s loaded BEFORE
// the grid-dependency sync; osmall/ssum read + out store after the sync.
// add = (os_part0 + os_part1) / S[b][pooled]: normalization deferred here —
// mathematically identical to normalizing attn (scalar factors out of the
// V-contraction).
#define UPS_STRIDE ((size_t)(BATCH * CH * HH * WWD / 4) / 8)   // float4 per slab
__global__ __launch_bounds__(256) void upsample_add(const float* __restrict__ x,
                                                    float* __restrict__ out) {
    size_t g = (size_t)blockIdx.x * 256u + threadIdx.x;
    float4 xv[8];
#pragma unroll
    for (int j = 0; j < 8; ++j)
        xv[j] = __ldcs(reinterpret_cast<const float4*>(x) + g + (size_t)j * UPS_STRIDE);

    cudaGridDependencySynchronize();   // out-GEMM done (=> energy+ssum done)

#pragma unroll
    for (int j = 0; j < 8; ++j) {
        size_t i = g + (size_t)j * UPS_STRIDE;
        unsigned w4 = (unsigned)(i & 63);
        size_t t = i >> 6;
        unsigned y = (unsigned)(t & 255);
        size_t bc = t >> 8;                                   // b*512 + c
        size_t oi = (bc << 10) + ((size_t)(y >> 3) << 5) + (w4 >> 1);
        size_t sidx = ((oi >> 19) << 10) + (oi & 1023u);      // b*NN + pooled m
        float add = (g_osmall[oi] + g_osmall[oi + (size_t)BATCH * CH * NN])
                    / g_ssum[sidx];
        __stcs(reinterpret_cast<float4*>(out) + i,
               make_float4(xv[j].x + add, xv[j].y + add, xv[j].z + add, xv[j].w + add));
    }
}

// ---------------- launch ----------------------------------------------------
extern "C" void kernel_launch(void* const* d_in, const int* in_sizes, int n_in,
                              void* d_out, int out_size) {
    const float* x  = (const float*)d_in[0];
    const float* Wq = (const float*)d_in[1];
    const float* bq = (const float*)d_in[2];
    const float* Wk = (const float*)d_in[3];
    const float* bk = (const float*)d_in[4];
    const float* Wv = (const float*)d_in[5];
    const float* bv = (const float*)d_in[6];
    float* out = (float*)d_out;

    __nv_bfloat16 *xf, *wcat, *qkv, *attn;
    float *osmall, *bcat;
    cudaGetSymbolAddress((void**)&xf,     g_xf);
    cudaGetSymbolAddress((void**)&wcat,   g_wcat);
    cudaGetSymbolAddress((void**)&bcat,   g_bcat);
    cudaGetSymbolAddress((void**)&qkv,    g_qkv);
    cudaGetSymbolAddress((void**)&attn,   g_attn);
    cudaGetSymbolAddress((void**)&osmall, g_osmall);

    auto QKV = gemm_bf16<false, false, 0, false>;   // bf16 + bias
    auto ENE = gemm_bf16<true,  false, 1, false>;   // bf16 exp + row sums
    auto OUT = gemm_bf16<false, true,  2, true>;    // fp32 k-split, PDL

    constexpr int SM_QKV = 2 * (128 * 72 + 64 * 136) * 2;   // 71680
    constexpr int SM_ENE = 2 * (64 * 136 + 64 * 136) * 2;   // 69632
    constexpr int SM_OUT = 2 * (128 * 72 + 128 * 72) * 2;   // 73728
    cudaFuncSetAttribute(QKV, cudaFuncAttributeMaxDynamicSharedMemorySize, SM_QKV);
    cudaFuncSetAttribute(ENE, cudaFuncAttributeMaxDynamicSharedMemorySize, SM_ENE);
    cudaFuncSetAttribute(OUT, cudaFuncAttributeMaxDynamicSharedMemorySize, SM_OUT);

    cudaLaunchAttribute pdl[1];
    pdl[0].id = cudaLaunchAttributeProgrammaticStreamSerialization;
    pdl[0].val.programmaticStreamSerializationAllowed = 1;

    pool_kernel<<<(BATCH * CH * NN) / 256, 256>>>(x);
    prep_w<<<(MQKV * CH + 255) / 256, 256>>>(Wq, Wk, Wv, bq, bk, bv);

    // QKV: qkv[b][m][n] = bias[m] + sum_c wcat[m][c] * xf[b][c][n]  (bf16 out)
    {
        dim3 g(NN / 128, MQKV / 128, BATCH);
        QKV<<<g, 256, SM_QKV>>>(
            wcat, 512, 0,
            xf,   NN,  (size_t)CH * NN,
            qkv,  NN,  (size_t)MQKV * NN, 0,
            bcat, CH);
    }
    // energy+exp: attn[b][n][m] = exp(0.125 * sum_k q[b][k][n]*kmat[b][k][m]),
    // row sums accumulated into g_ssum.  (softmax kernel eliminated)
    {
        dim3 g(NN / 128, NN / 128, BATCH);
        ENE<<<g, 256, SM_ENE>>>(
            qkv,           NN, (size_t)MQKV * NN,
            qkv + 64 * NN, NN, (size_t)MQKV * NN,
            attn,          NN, (size_t)NN * NN, 0,
            nullptr, KD);
    }
    // out-GEMM (PDL after energy): prefetch V chunk0 (finalized by QKV,
    // before energy started), gridsync, then attn. k-split x2, fp32 out.
    {
        cudaLaunchConfig_t cfg = {};
        cfg.gridDim = dim3(NN / 128, CH / 128, BATCH * 2);
        cfg.blockDim = dim3(256, 1, 1);
        cfg.dynamicSmemBytes = SM_OUT;
        cfg.stream = 0;
        cfg.attrs = pdl; cfg.numAttrs = 1;
        cudaLaunchKernelEx(&cfg, OUT,
            (const __nv_bfloat16*)(qkv + 128 * NN), NN, (size_t)MQKV * NN,
            (const __nv_bfloat16*)attn,             NN, (size_t)NN * NN,
            (void*)osmall, NN, (size_t)CH * NN, (size_t)BATCH * CH * NN,
            (const float*)nullptr, NN / 2);
    }
    // upsample (PDL after out-GEMM): deep 8-slab x prefetch, gridsync, store.
    {
        cudaLaunchConfig_t cfg = {};
        cfg.gridDim  = dim3((unsigned)(UPS_STRIDE / 256), 1, 1);
        cfg.blockDim = dim3(256, 1, 1);
        cfg.dynamicSmemBytes = 0;
        cfg.stream = 0;
        cfg.attrs = pdl; cfg.numAttrs = 1;
        cudaLaunchKernelEx(&cfg, upsample_add, x, out);
    }
}